// round 4
// baseline (speedup 1.0000x reference)
#include <cuda_runtime.h>
#include <math.h>

#define L_SEQ 2048
#define BATCH 2
#define EMB   1024
#define NH    16
#define DQKh  128     // per-head qk dim
#define QKD   2048    // total qk dim
#define DVh   64      // per-head v dim
#define NROWS 4096    // L*B

// ---------------- scratch (static device globals; no allocation) ------------
__device__ float g_qlin[(size_t)NROWS * QKD];   // 32MB  relu(q proj)*scale
__device__ float g_klin[(size_t)NROWS * QKD];   // 32MB  relu(k proj)
__device__ float g_vlin[(size_t)NROWS * EMB];   // 16MB  v proj
__device__ float g_attn[(size_t)NROWS * EMB];   // 16MB  attention output (l,b,e)
__device__ int   g_ws[NH * L_SEQ];              // per (head,row) window start

// ---------------- mask window-start table -----------------------------------
// Faithful port of _one_mask: head h keeps dims [ws, ws+32) of 128,
// ws = mm*h with rn = 96/h+1, i=l/rn, m=l%rn, mm = (i&1)? rn-1-m : m.
__global__ void build_ws_kernel() {
    int idx = blockIdx.x * blockDim.x + threadIdx.x;
    if (idx >= NH * L_SEQ) return;
    int h = idx / L_SEQ, l = idx % L_SEQ;
    int ws = 0;
    if (h > 0) {
        int rn = 96 / h + 1;
        int i = l / rn, m = l % rn;
        int mm = (i & 1) ? (rn - 1 - m) : m;
        ws = mm * h;
    }
    g_ws[idx] = ws;
}

// ---------------- SGEMM: C[M,N] = epilogue(A[M,K] @ W[N,K]^T + bias) --------
// MODE 0: +bias    MODE 1: relu(+bias)*scale    MODE 2: relu(+bias)
// BM=BN=128, BK=8, 256 threads, 8x8 per thread.
template <int MODE>
__global__ void __launch_bounds__(256) sgemm_bias(
    const float* __restrict__ A, const float* __restrict__ W,
    const float* __restrict__ bias, float* __restrict__ C,
    int M, int N, int K, float scale)
{
    __shared__ float As[8][128];
    __shared__ float Bs[8][128];
    int tid = threadIdx.x;
    int tx = tid & 15, ty = tid >> 4;
    int m0 = blockIdx.y * 128, n0 = blockIdx.x * 128;
    int lrow = tid >> 1;
    int lcol = (tid & 1) * 4;
    const float* Ap = A + (size_t)(m0 + lrow) * K + lcol;
    const float* Wp = W + (size_t)(n0 + lrow) * K + lcol;

    float acc[8][8] = {};
    for (int kt = 0; kt < K; kt += 8) {
        float4 av = *(const float4*)(Ap + kt);
        float4 bv = *(const float4*)(Wp + kt);
        As[lcol + 0][lrow] = av.x; As[lcol + 1][lrow] = av.y;
        As[lcol + 2][lrow] = av.z; As[lcol + 3][lrow] = av.w;
        Bs[lcol + 0][lrow] = bv.x; Bs[lcol + 1][lrow] = bv.y;
        Bs[lcol + 2][lrow] = bv.z; Bs[lcol + 3][lrow] = bv.w;
        __syncthreads();
        #pragma unroll
        for (int kk = 0; kk < 8; kk++) {
            float a[8], bb[8];
            #pragma unroll
            for (int i = 0; i < 8; i++) a[i]  = As[kk][ty * 8 + i];
            #pragma unroll
            for (int j = 0; j < 8; j++) bb[j] = Bs[kk][tx * 8 + j];
            #pragma unroll
            for (int i = 0; i < 8; i++)
                #pragma unroll
                for (int j = 0; j < 8; j++)
                    acc[i][j] += a[i] * bb[j];
        }
        __syncthreads();
    }
    #pragma unroll
    for (int i = 0; i < 8; i++) {
        int r = m0 + ty * 8 + i;
        #pragma unroll
        for (int j = 0; j < 8; j++) {
            int c = n0 + tx * 8 + j;
            float v = acc[i][j] + bias[c];
            if (MODE >= 1) v = fmaxf(v, 0.0f);
            if (MODE == 1) v *= scale;
            C[(size_t)r * N + c] = v;
        }
    }
}

// ---------------- attention: flash-style masked linear attention ------------
// grid: (L/64, B*H). Block: 256 threads, 64 q-rows, loop 64-wide s-tiles.
// W[l,s] = dot(maskQ(q[l]), maskK(k[s])) + [s global] dot(q[l], k[s])
// out[l] = (sum_s W[l,s] v[s]) / max(sum_s W[l,s], 1e-12)
__global__ void __launch_bounds__(256) attn_kernel(
    const float* __restrict__ qlin, const float* __restrict__ klin,
    const float* __restrict__ vlin, float* __restrict__ attn)
{
    extern __shared__ float sm[];
    float* Qs = sm;                 // 64 x 129 (masked q tile, padded)
    float* Ks = Qs + 64 * 129;      // 64 x 129 (masked k tile)
    float* Ss = Ks + 64 * 129;      // 64 x 65  (score tile)
    float* Vs = Ss + 64 * 65;       // 64 x 65  (v tile)
    float* dn = Vs + 64 * 65;       // 64       (denominator accum)

    int tid = threadIdx.x;
    int tx = tid & 15, ty = tid >> 4;
    int bh = blockIdx.y;
    int b = bh >> 4, h = bh & 15;
    int l0 = blockIdx.x * 64;

    // load Q tile (masked)
    for (int idx = tid; idx < 64 * 128; idx += 256) {
        int li = idx >> 7, d = idx & 127;
        int l = l0 + li;
        float qv = qlin[(size_t)(l * BATCH + b) * QKD + h * DQKh + d];
        int ws = g_ws[h * L_SEQ + l];
        bool keep = (h == 0) || ((unsigned)(d - ws) < 32u);
        Qs[li * 129 + d] = keep ? qv : 0.0f;
    }
    if (tid < 64) dn[tid] = 0.0f;

    float o[4][4] = {};

    for (int st = 0; st < 32; st++) {
        int s0 = st * 64;
        __syncthreads();  // protects Qs load (1st iter) + Ss/Vs/Ks reuse

        // load K tile (masked) + V tile
        for (int idx = tid; idx < 64 * 128; idx += 256) {
            int si = idx >> 7, d = idx & 127;
            int s = s0 + si;
            float kv = klin[(size_t)(s * BATCH + b) * QKD + h * DQKh + d];
            int ws = g_ws[h * L_SEQ + s];
            bool keep = (h == 0) || ((unsigned)(d - ws) < 32u);
            Ks[si * 129 + d] = keep ? kv : 0.0f;
        }
        for (int idx = tid; idx < 64 * 64; idx += 256) {
            int si = idx >> 6, d = idx & 63;
            Vs[si * 65 + d] = vlin[(size_t)((s0 + si) * BATCH + b) * EMB + h * DVh + d];
        }
        __syncthreads();

        // S = Qs @ Ks^T  (4x4 per thread)
        float sacc[4][4] = {};
        #pragma unroll 4
        for (int d = 0; d < 128; d++) {
            float a[4], bb[4];
            #pragma unroll
            for (int i = 0; i < 4; i++) a[i]  = Qs[(ty * 4 + i) * 129 + d];
            #pragma unroll
            for (int j = 0; j < 4; j++) bb[j] = Ks[(tx * 4 + j) * 129 + d];
            #pragma unroll
            for (int i = 0; i < 4; i++)
                #pragma unroll
                for (int j = 0; j < 4; j++)
                    sacc[i][j] += a[i] * bb[j];
        }

        // global-key correction: s in [0,16) or [2032,2048) add full q.k dot
        if (st == 0 || st == 31) {
            int g0 = (st == 0) ? 0 : 48;
            __syncthreads();
            for (int idx = tid; idx < 16 * 128; idx += 256) {   // reload 16 rows, unmasked
                int si = idx >> 7, d = idx & 127;
                int s = s0 + g0 + si;
                Ks[(g0 + si) * 129 + d] =
                    klin[(size_t)(s * BATCH + b) * QKD + h * DQKh + d];
            }
            __syncthreads();
            #pragma unroll
            for (int j = 0; j < 4; j++) {
                int sl = tx * 4 + j;
                if ((unsigned)(sl - g0) < 16u) {
                    #pragma unroll
                    for (int i = 0; i < 4; i++) {
                        int l = l0 + ty * 4 + i;
                        const float* qrow =
                            qlin + (size_t)(l * BATCH + b) * QKD + h * DQKh;
                        float acc = 0.0f;
                        for (int d = 0; d < 128; d++)
                            acc += qrow[d] * Ks[sl * 129 + d];
                        sacc[i][j] += acc;
                    }
                }
            }
        }

        // stage S in shared
        #pragma unroll
        for (int i = 0; i < 4; i++)
            #pragma unroll
            for (int j = 0; j < 4; j++)
                Ss[(ty * 4 + i) * 65 + tx * 4 + j] = sacc[i][j];
        __syncthreads();

        // denominator row-sums (conflict-free via pad-65)
        if (tid < 64) {
            float s = 0.0f;
            #pragma unroll 8
            for (int j = 0; j < 64; j++) s += Ss[tid * 65 + j];
            dn[tid] += s;
        }

        // Out += S @ V
        #pragma unroll 4
        for (int sk = 0; sk < 64; sk++) {
            float a[4], bb[4];
            #pragma unroll
            for (int i = 0; i < 4; i++) a[i]  = Ss[(ty * 4 + i) * 65 + sk];
            #pragma unroll
            for (int j = 0; j < 4; j++) bb[j] = Vs[sk * 65 + tx * 4 + j];
            #pragma unroll
            for (int i = 0; i < 4; i++)
                #pragma unroll
                for (int j = 0; j < 4; j++)
                    o[i][j] += a[i] * bb[j];
        }
    }
    __syncthreads();

    #pragma unroll
    for (int i = 0; i < 4; i++) {
        int l = l0 + ty * 4 + i;
        float inv = 1.0f / fmaxf(dn[ty * 4 + i], 1e-12f);
        #pragma unroll
        for (int j = 0; j < 4; j++) {
            attn[(size_t)(l * BATCH + b) * EMB + h * DVh + tx * 4 + j] =
                o[i][j] * inv;
        }
    }
}

// ---------------- launch -----------------------------------------------------
extern "C" void kernel_launch(void* const* d_in, const int* in_sizes, int n_in,
                              void* d_out, int out_size)
{
    (void)in_sizes; (void)n_in; (void)out_size;
    const float* query = (const float*)d_in[0];
    const float* key_  = (const float*)d_in[1];
    const float* value = (const float*)d_in[2];
    const float* Wq    = (const float*)d_in[3];
    const float* bq    = (const float*)d_in[4];
    const float* Wk    = (const float*)d_in[5];
    const float* bk    = (const float*)d_in[6];
    const float* Wv    = (const float*)d_in[7];
    const float* bv    = (const float*)d_in[8];
    const float* Wo    = (const float*)d_in[9];
    const float* bo    = (const float*)d_in[10];
    float* out = (float*)d_out;

    float *qlin, *klin, *vlin, *attn;
    cudaGetSymbolAddress((void**)&qlin, g_qlin);
    cudaGetSymbolAddress((void**)&klin, g_klin);
    cudaGetSymbolAddress((void**)&vlin, g_vlin);
    cudaGetSymbolAddress((void**)&attn, g_attn);

    const size_t ATTN_SMEM = (2 * 64 * 129 + 2 * 64 * 65 + 64) * sizeof(float);
    cudaFuncSetAttribute(attn_kernel,
                         cudaFuncAttributeMaxDynamicSharedMemorySize,
                         (int)ATTN_SMEM);

    build_ws_kernel<<<(NH * L_SEQ + 255) / 256, 256>>>();

    float scale = 1.0f / sqrtf((float)QKD);
    // q = relu(query @ Wq^T + bq) * scale   : M=4096 N=2048 K=1024
    sgemm_bias<1><<<dim3(QKD / 128, NROWS / 128), 256>>>(
        query, Wq, bq, qlin, NROWS, QKD, EMB, scale);
    // k = relu(key @ Wk^T + bk)
    sgemm_bias<2><<<dim3(QKD / 128, NROWS / 128), 256>>>(
        key_, Wk, bk, klin, NROWS, QKD, EMB, 1.0f);
    // v = value @ Wv^T + bv                 : N=1024
    sgemm_bias<0><<<dim3(EMB / 128, NROWS / 128), 256>>>(
        value, Wv, bv, vlin, NROWS, EMB, EMB, 1.0f);

    // attention
    attn_kernel<<<dim3(L_SEQ / 64, BATCH * NH), 256, ATTN_SMEM>>>(
        qlin, klin, vlin, attn);

    // out = attn @ Wo^T + bo
    sgemm_bias<0><<<dim3(EMB / 128, NROWS / 128), 256>>>(
        attn, Wo, bo, out, NROWS, EMB, EMB, 1.0f);
}

// round 7
// speedup vs baseline: 2.1645x; 2.1645x over previous
#include <cuda_runtime.h>
#include <cuda_bf16.h>
#include <stdint.h>
#include <math.h>

#define L_SEQ 2048
#define BATCH 2
#define EMB   1024
#define NH    16
#define DQKh  128
#define QKD   2048
#define DVh   64
#define NROWS 4096

typedef __nv_bfloat16 bf16;

// ---------------- scratch (static device globals; no allocation) -------------
__device__ bf16 g_inq_hi[(size_t)NROWS*EMB];
__device__ bf16 g_inq_lo[(size_t)NROWS*EMB];
__device__ bf16 g_ink_hi[(size_t)NROWS*EMB];
__device__ bf16 g_ink_lo[(size_t)NROWS*EMB];
__device__ bf16 g_inv_hi[(size_t)NROWS*EMB];
__device__ bf16 g_inv_lo[(size_t)NROWS*EMB];
__device__ bf16 g_wq_hi[(size_t)QKD*EMB];
__device__ bf16 g_wq_lo[(size_t)QKD*EMB];
__device__ bf16 g_wk_hi[(size_t)QKD*EMB];
__device__ bf16 g_wk_lo[(size_t)QKD*EMB];
__device__ bf16 g_wv_hi[(size_t)EMB*EMB];
__device__ bf16 g_wv_lo[(size_t)EMB*EMB];
__device__ bf16 g_wo_hi[(size_t)EMB*EMB];
__device__ bf16 g_wo_lo[(size_t)EMB*EMB];
__device__ bf16 g_q_hi[(size_t)BATCH*NH*L_SEQ*DQKh];
__device__ bf16 g_q_lo[(size_t)BATCH*NH*L_SEQ*DQKh];
__device__ bf16 g_k_hi[(size_t)BATCH*NH*L_SEQ*DQKh];
__device__ bf16 g_k_lo[(size_t)BATCH*NH*L_SEQ*DQKh];
__device__ bf16 g_v_hi[(size_t)BATCH*NH*L_SEQ*DVh];
__device__ bf16 g_v_lo[(size_t)BATCH*NH*L_SEQ*DVh];
__device__ bf16 g_at_hi[(size_t)NROWS*EMB];
__device__ bf16 g_at_lo[(size_t)NROWS*EMB];
__device__ float g_corr[(size_t)BATCH*NH*L_SEQ*32];
__device__ int   g_ws[NH*L_SEQ];

// ---------------- helpers ----------------------------------------------------
__device__ __forceinline__ void mma_bf16(float c[4], const uint32_t a[4],
                                         uint32_t b0, uint32_t b1) {
    asm volatile(
        "mma.sync.aligned.m16n8k16.row.col.f32.bf16.bf16.f32 "
        "{%0,%1,%2,%3},{%4,%5,%6,%7},{%8,%9},{%0,%1,%2,%3};"
        : "+f"(c[0]), "+f"(c[1]), "+f"(c[2]), "+f"(c[3])
        : "r"(a[0]), "r"(a[1]), "r"(a[2]), "r"(a[3]), "r"(b0), "r"(b1));
}

// mask a packed bf16 pair covering dims (d, d+1): keep iff dim in [ws, ws+32)
__device__ __forceinline__ uint32_t mpair(uint32_t v, int d, int ws) {
    uint32_t m = 0;
    if ((unsigned)(d - ws) < 32u)     m |= 0x0000FFFFu;
    if ((unsigned)(d + 1 - ws) < 32u) m |= 0xFFFF0000u;
    return v & m;
}

__device__ __forceinline__ void split_pack(float x, float y,
                                           uint32_t& hi, uint32_t& lo) {
    __nv_bfloat16 hx = __float2bfloat16(x), hy = __float2bfloat16(y);
    __nv_bfloat162 ph; ph.x = hx; ph.y = hy;
    hi = *(uint32_t*)&ph;
    __nv_bfloat162 pl;
    pl.x = __float2bfloat16(x - __bfloat162float(hx));
    pl.y = __float2bfloat16(y - __bfloat162float(hy));
    lo = *(uint32_t*)&pl;
}

__device__ __forceinline__ void store_hl(bf16* hip, bf16* lop, size_t idx,
                                         float v0, float v1) {
    __nv_bfloat16 h0 = __float2bfloat16(v0), h1 = __float2bfloat16(v1);
    __nv_bfloat162 hh; hh.x = h0; hh.y = h1;
    *(__nv_bfloat162*)(hip + idx) = hh;
    __nv_bfloat162 ll;
    ll.x = __float2bfloat16(v0 - __bfloat162float(h0));
    ll.y = __float2bfloat16(v1 - __bfloat162float(h1));
    *(__nv_bfloat162*)(lop + idx) = ll;
}

// ---------------- setup kernels ----------------------------------------------
__global__ void build_ws_kernel() {
    int idx = blockIdx.x * blockDim.x + threadIdx.x;
    if (idx >= NH * L_SEQ) return;
    int h = idx / L_SEQ, l = idx % L_SEQ;
    int ws = 0;
    if (h > 0) {
        int rn = 96 / h + 1;
        int i = l / rn, m = l % rn;
        int mm = (i & 1) ? (rn - 1 - m) : m;
        ws = mm * h;
    }
    g_ws[idx] = ws;
}

__global__ void cvt_kernel(const float* __restrict__ src, bf16* __restrict__ hi,
                           bf16* __restrict__ lo, int n) {
    int i = blockIdx.x * blockDim.x + threadIdx.x;
    if (i < n) {
        float x = src[i];
        bf16 h = __float2bfloat16(x);
        hi[i] = h;
        lo[i] = __float2bfloat16(x - __bfloat162float(h));
    }
}

// ---------------- MMA GEMM: C = epi(A[M,K] @ W[N,K]^T + bias) ----------------
// OMODE 0: fp32 out [M,N]
// OMODE 1: relu*scale -> bf16 hi/lo planes [(b h) l d], D=128  (q,k)
// OMODE 2: linear     -> bf16 hi/lo planes [(b h) l d], D=64   (v)
template <int OMODE>
__global__ void __launch_bounds__(256) mma_gemm(
    const bf16* __restrict__ Ahi, const bf16* __restrict__ Alo,
    const bf16* __restrict__ Whi, const bf16* __restrict__ Wlo,
    const float* __restrict__ bias,
    float* __restrict__ Cf, bf16* __restrict__ Ohi, bf16* __restrict__ Olo,
    int N, int K, float scale)
{
    __shared__ bf16 sAh[128 * 24];
    __shared__ bf16 sAl[128 * 24];
    __shared__ bf16 sWh[128 * 24];
    __shared__ bf16 sWl[128 * 24];

    int tid = threadIdx.x;
    int wid = tid >> 5, lane = tid & 31;
    int r = lane >> 2, qc = lane & 3;
    int warp_m = (wid >> 1) * 32, warp_n = (wid & 1) * 64;
    int m0 = blockIdx.y * 128, n0 = blockIdx.x * 128;

    int lrow = tid >> 1, lpart = (tid & 1) * 8;
    const bf16* pAh = Ahi + (size_t)(m0 + lrow) * K + lpart;
    const bf16* pAl = Alo + (size_t)(m0 + lrow) * K + lpart;
    const bf16* pWh = Whi + (size_t)(n0 + lrow) * K + lpart;
    const bf16* pWl = Wlo + (size_t)(n0 + lrow) * K + lpart;
    int sidx = lrow * 24 + lpart;

    float acc[2][8][4] = {};

    for (int kt = 0; kt < K; kt += 16) {
        *(uint4*)&sAh[sidx] = *(const uint4*)(pAh + kt);
        *(uint4*)&sAl[sidx] = *(const uint4*)(pAl + kt);
        *(uint4*)&sWh[sidx] = *(const uint4*)(pWh + kt);
        *(uint4*)&sWl[sidx] = *(const uint4*)(pWl + kt);
        __syncthreads();

        uint32_t afr[2][2][4];
        #pragma unroll
        for (int mt = 0; mt < 2; mt++) {
            int row = warp_m + mt * 16 + r;
            afr[mt][0][0] = *(const uint32_t*)&sAh[row * 24 + 2 * qc];
            afr[mt][0][1] = *(const uint32_t*)&sAh[(row + 8) * 24 + 2 * qc];
            afr[mt][0][2] = *(const uint32_t*)&sAh[row * 24 + 2 * qc + 8];
            afr[mt][0][3] = *(const uint32_t*)&sAh[(row + 8) * 24 + 2 * qc + 8];
            afr[mt][1][0] = *(const uint32_t*)&sAl[row * 24 + 2 * qc];
            afr[mt][1][1] = *(const uint32_t*)&sAl[(row + 8) * 24 + 2 * qc];
            afr[mt][1][2] = *(const uint32_t*)&sAl[row * 24 + 2 * qc + 8];
            afr[mt][1][3] = *(const uint32_t*)&sAl[(row + 8) * 24 + 2 * qc + 8];
        }
        #pragma unroll
        for (int nt = 0; nt < 8; nt++) {
            int wrow = warp_n + nt * 8 + r;
            uint32_t bh0 = *(const uint32_t*)&sWh[wrow * 24 + 2 * qc];
            uint32_t bh1 = *(const uint32_t*)&sWh[wrow * 24 + 2 * qc + 8];
            uint32_t bl0 = *(const uint32_t*)&sWl[wrow * 24 + 2 * qc];
            uint32_t bl1 = *(const uint32_t*)&sWl[wrow * 24 + 2 * qc + 8];
            #pragma unroll
            for (int mt = 0; mt < 2; mt++) {
                mma_bf16(acc[mt][nt], afr[mt][0], bh0, bh1);
                mma_bf16(acc[mt][nt], afr[mt][0], bl0, bl1);
                mma_bf16(acc[mt][nt], afr[mt][1], bh0, bh1);
            }
        }
        __syncthreads();
    }

    #pragma unroll
    for (int mt = 0; mt < 2; mt++) {
        #pragma unroll
        for (int nt = 0; nt < 8; nt++) {
            int row0 = m0 + warp_m + mt * 16 + r;
            int row1 = row0 + 8;
            int col  = n0 + warp_n + nt * 8 + 2 * qc;
            float b0f = bias[col], b1f = bias[col + 1];
            float v00 = acc[mt][nt][0] + b0f, v01 = acc[mt][nt][1] + b1f;
            float v10 = acc[mt][nt][2] + b0f, v11 = acc[mt][nt][3] + b1f;
            if (OMODE == 1) {
                v00 = fmaxf(v00, 0.f) * scale; v01 = fmaxf(v01, 0.f) * scale;
                v10 = fmaxf(v10, 0.f) * scale; v11 = fmaxf(v11, 0.f) * scale;
            }
            if (OMODE == 0) {
                *(float2*)(Cf + (size_t)row0 * N + col) = make_float2(v00, v01);
                *(float2*)(Cf + (size_t)row1 * N + col) = make_float2(v10, v11);
            } else if (OMODE == 1) {
                int h = col >> 7, d = col & 127;
                store_hl(Ohi, Olo,
                    ((size_t)((row0 & 1) * NH + h) * L_SEQ + (row0 >> 1)) * DQKh + d,
                    v00, v01);
                store_hl(Ohi, Olo,
                    ((size_t)((row1 & 1) * NH + h) * L_SEQ + (row1 >> 1)) * DQKh + d,
                    v10, v11);
            } else {
                int h = col >> 6, d = col & 63;
                store_hl(Ohi, Olo,
                    ((size_t)((row0 & 1) * NH + h) * L_SEQ + (row0 >> 1)) * DVh + d,
                    v00, v01);
                store_hl(Ohi, Olo,
                    ((size_t)((row1 & 1) * NH + h) * L_SEQ + (row1 >> 1)) * DVh + d,
                    v10, v11);
            }
        }
    }
}

// ---------------- global-key correction: corr[y,l,j] = q[l]·kglobal[j] -------
__global__ void __launch_bounds__(256) corr_kernel(
    const bf16* __restrict__ qhi, const bf16* __restrict__ qlo,
    const bf16* __restrict__ khi, const bf16* __restrict__ klo,
    float* __restrict__ corr)
{
    __shared__ float sKg[32][128];
    int tid = threadIdx.x;
    int y = blockIdx.y;
    int l0 = blockIdx.x * 128;

    for (int i = tid; i < 32 * 128; i += 256) {
        int j = i >> 7, d = i & 127;
        int s = (j < 16) ? j : (L_SEQ - 32 + j);
        size_t g = ((size_t)y * L_SEQ + s) * DQKh + d;
        sKg[j][d] = __bfloat162float(khi[g]) + __bfloat162float(klo[g]);
    }
    __syncthreads();

    int l = l0 + (tid >> 1);
    int jb = (tid & 1) * 16;
    float acc[16] = {};
    size_t qb = ((size_t)y * L_SEQ + l) * DQKh;
    for (int d = 0; d < 128; d += 2) {
        uint32_t ph = *(const uint32_t*)(qhi + qb + d);
        uint32_t pl = *(const uint32_t*)(qlo + qb + d);
        __nv_bfloat162 h2 = *(__nv_bfloat162*)&ph;
        __nv_bfloat162 l2 = *(__nv_bfloat162*)&pl;
        float q0 = __bfloat162float(h2.x) + __bfloat162float(l2.x);
        float q1 = __bfloat162float(h2.y) + __bfloat162float(l2.y);
        #pragma unroll
        for (int j = 0; j < 16; j++)
            acc[j] += q0 * sKg[jb + j][d] + q1 * sKg[jb + j][d + 1];
    }
    float* cp = corr + ((size_t)y * L_SEQ + l) * 32 + jb;
    #pragma unroll
    for (int j = 0; j < 16; j++) cp[j] = acc[j];
}

// ---------------- attention (tensor-core masked linear attention) ------------
// grid (L/64, B*NH), 128 threads (4 warps x 16 q-rows). Q frags in registers.
__global__ void __launch_bounds__(128) attn_mma(
    const bf16* __restrict__ qhi, const bf16* __restrict__ qlo,
    const bf16* __restrict__ khi, const bf16* __restrict__ klo,
    const bf16* __restrict__ vhi, const bf16* __restrict__ vlo,
    const float* __restrict__ corr,
    bf16* __restrict__ ohi, bf16* __restrict__ olo)
{
    extern __shared__ uint8_t sraw[];
    bf16* sKhi = (bf16*)sraw;                       // 64 x 136
    bf16* sKlo = sKhi + 64 * 136;
    uint32_t* sVhiP = (uint32_t*)(sKlo + 64 * 136); // 32 x 72 (s-row pairs)
    uint32_t* sVloP = sVhiP + 32 * 72;

    int tid = threadIdx.x;
    int wid = tid >> 5, lane = tid & 31;
    int r = lane >> 2, qc = lane & 3;
    int y = blockIdx.y;
    int h = y & 15;
    int l0 = blockIdx.x * 64;
    int lr = l0 + wid * 16 + r;

    // masked Q fragments in registers (8 k-steps of 16 dims)
    uint32_t qa[8][2][4];
    {
        size_t rb0 = ((size_t)y * L_SEQ + lr) * DQKh;
        size_t rb1 = rb0 + 8 * DQKh;
        int ws0 = (h == 0) ? 0 : g_ws[h * L_SEQ + lr];
        int ws1 = (h == 0) ? 0 : g_ws[h * L_SEQ + lr + 8];
        #pragma unroll
        for (int ks = 0; ks < 8; ks++) {
            int d0 = ks * 16 + 2 * qc;
            int d2 = d0 + 8;
            uint32_t a0 = *(const uint32_t*)(qhi + rb0 + d0);
            uint32_t a1 = *(const uint32_t*)(qhi + rb1 + d0);
            uint32_t a2 = *(const uint32_t*)(qhi + rb0 + d2);
            uint32_t a3 = *(const uint32_t*)(qhi + rb1 + d2);
            uint32_t c0 = *(const uint32_t*)(qlo + rb0 + d0);
            uint32_t c1 = *(const uint32_t*)(qlo + rb1 + d0);
            uint32_t c2 = *(const uint32_t*)(qlo + rb0 + d2);
            uint32_t c3 = *(const uint32_t*)(qlo + rb1 + d2);
            if (h != 0) {
                a0 = mpair(a0, d0, ws0); a1 = mpair(a1, d0, ws1);
                a2 = mpair(a2, d2, ws0); a3 = mpair(a3, d2, ws1);
                c0 = mpair(c0, d0, ws0); c1 = mpair(c1, d0, ws1);
                c2 = mpair(c2, d2, ws0); c3 = mpair(c3, d2, ws1);
            }
            qa[ks][0][0] = a0; qa[ks][0][1] = a1;
            qa[ks][0][2] = a2; qa[ks][0][3] = a3;
            qa[ks][1][0] = c0; qa[ks][1][1] = c1;
            qa[ks][1][2] = c2; qa[ks][1][3] = c3;
        }
    }

    float oacc[8][4] = {};
    float den0 = 0.f, den1 = 0.f;

    for (int st = 0; st < 32; st++) {
        int s0 = st * 64;

        // masked K tile
        #pragma unroll
        for (int i = 0; i < 8; i++) {
            int f = tid + i * 128;
            int srow = f >> 4, dch = (f & 15) * 8;
            int wsr = (h == 0) ? 0 : g_ws[h * L_SEQ + s0 + srow];
            size_t gb = ((size_t)y * L_SEQ + s0 + srow) * DQKh + dch;
            uint4 v = *(const uint4*)(khi + gb);
            uint4 w = *(const uint4*)(klo + gb);
            if (h != 0) {
                v.x = mpair(v.x, dch, wsr);     v.y = mpair(v.y, dch + 2, wsr);
                v.z = mpair(v.z, dch + 4, wsr); v.w = mpair(v.w, dch + 6, wsr);
                w.x = mpair(w.x, dch, wsr);     w.y = mpair(w.y, dch + 2, wsr);
                w.z = mpair(w.z, dch + 4, wsr); w.w = mpair(w.w, dch + 6, wsr);
            }
            *(uint4*)&sKhi[srow * 136 + dch] = v;
            *(uint4*)&sKlo[srow * 136 + dch] = w;
        }
        // V tile with (s,s+1) pairing
        #pragma unroll
        for (int ii = 0; ii < 2; ii++) {
            int i = tid + ii * 128;
            int s2 = i >> 3, ch = i & 7;
            size_t gb = ((size_t)y * L_SEQ + s0 + 2 * s2) * DVh + ch * 8;
            uint4 a = *(const uint4*)(vhi + gb);
            uint4 bq = *(const uint4*)(vhi + gb + DVh);
            uint32_t* dst = &sVhiP[s2 * 72 + ch * 8];
            ((uint4*)dst)[0] = make_uint4(
                __byte_perm(a.x, bq.x, 0x5410), __byte_perm(a.x, bq.x, 0x7632),
                __byte_perm(a.y, bq.y, 0x5410), __byte_perm(a.y, bq.y, 0x7632));
            ((uint4*)dst)[1] = make_uint4(
                __byte_perm(a.z, bq.z, 0x5410), __byte_perm(a.z, bq.z, 0x7632),
                __byte_perm(a.w, bq.w, 0x5410), __byte_perm(a.w, bq.w, 0x7632));
            uint4 c = *(const uint4*)(vlo + gb);
            uint4 dq = *(const uint4*)(vlo + gb + DVh);
            uint32_t* dst2 = &sVloP[s2 * 72 + ch * 8];
            ((uint4*)dst2)[0] = make_uint4(
                __byte_perm(c.x, dq.x, 0x5410), __byte_perm(c.x, dq.x, 0x7632),
                __byte_perm(c.y, dq.y, 0x5410), __byte_perm(c.y, dq.y, 0x7632));
            ((uint4*)dst2)[1] = make_uint4(
                __byte_perm(c.z, dq.z, 0x5410), __byte_perm(c.z, dq.z, 0x7632),
                __byte_perm(c.w, dq.w, 0x5410), __byte_perm(c.w, dq.w, 0x7632));
        }
        __syncthreads();

        // S = Qmasked @ Kmasked^T  (3-term split)
        float sacc[8][4] = {};
        #pragma unroll
        for (int ks = 0; ks < 8; ks++) {
            #pragma unroll
            for (int nt = 0; nt < 8; nt++) {
                int so = (nt * 8 + r) * 136 + ks * 16 + 2 * qc;
                uint32_t bh0 = *(const uint32_t*)&sKhi[so];
                uint32_t bh1 = *(const uint32_t*)&sKhi[so + 8];
                uint32_t bl0 = *(const uint32_t*)&sKlo[so];
                uint32_t bl1 = *(const uint32_t*)&sKlo[so + 8];
                mma_bf16(sacc[nt], qa[ks][0], bh0, bh1);
                mma_bf16(sacc[nt], qa[ks][0], bl0, bl1);
                mma_bf16(sacc[nt], qa[ks][1], bh0, bh1);
            }
        }

        // global-key correction (adds q·kg on the 32 global columns)
        if (st == 0) {
            #pragma unroll
            for (int nt = 0; nt < 2; nt++) {
                size_t c0i = ((size_t)y * L_SEQ + lr) * 32 + nt * 8 + 2 * qc;
                size_t c1i = c0i + 8 * 32;
                sacc[nt][0] += corr[c0i]; sacc[nt][1] += corr[c0i + 1];
                sacc[nt][2] += corr[c1i]; sacc[nt][3] += corr[c1i + 1];
            }
        } else if (st == 31) {
            #pragma unroll
            for (int i2 = 0; i2 < 2; i2++) {
                int nt = 6 + i2;
                size_t c0i = ((size_t)y * L_SEQ + lr) * 32 + 16 + i2 * 8 + 2 * qc;
                size_t c1i = c0i + 8 * 32;
                sacc[nt][0] += corr[c0i]; sacc[nt][1] += corr[c0i + 1];
                sacc[nt][2] += corr[c1i]; sacc[nt][3] += corr[c1i + 1];
            }
        }

        // denominator partials
        #pragma unroll
        for (int nt = 0; nt < 8; nt++) {
            den0 += sacc[nt][0] + sacc[nt][1];
            den1 += sacc[nt][2] + sacc[nt][3];
        }

        // O += S @ V : S frags re-split to bf16 as A fragments
        #pragma unroll
        for (int kk = 0; kk < 4; kk++) {
            uint32_t ahi[4], alo[4];
            split_pack(sacc[2 * kk][0],     sacc[2 * kk][1],     ahi[0], alo[0]);
            split_pack(sacc[2 * kk][2],     sacc[2 * kk][3],     ahi[1], alo[1]);
            split_pack(sacc[2 * kk + 1][0], sacc[2 * kk + 1][1], ahi[2], alo[2]);
            split_pack(sacc[2 * kk + 1][2], sacc[2 * kk + 1][3], ahi[3], alo[3]);
            #pragma unroll
            for (int nt = 0; nt < 8; nt++) {
                int vo = (kk * 8 + qc) * 72 + nt * 8 + r;
                uint32_t bh0 = sVhiP[vo], bh1 = sVhiP[vo + 4 * 72];
                uint32_t bl0 = sVloP[vo], bl1 = sVloP[vo + 4 * 72];
                mma_bf16(oacc[nt], ahi, bh0, bh1);
                mma_bf16(oacc[nt], ahi, bl0, bl1);
                mma_bf16(oacc[nt], alo, bh0, bh1);
            }
        }
        __syncthreads();
    }

    // reduce denominators across the quad (qc lanes)
    den0 += __shfl_xor_sync(0xffffffffu, den0, 1);
    den0 += __shfl_xor_sync(0xffffffffu, den0, 2);
    den1 += __shfl_xor_sync(0xffffffffu, den1, 1);
    den1 += __shfl_xor_sync(0xffffffffu, den1, 2);
    float inv0 = 1.0f / fmaxf(den0, 1e-12f);
    float inv1 = 1.0f / fmaxf(den1, 1e-12f);

    // store normalized output as hi/lo planes, row = l*BATCH+b, col = h*64+d
    int b = y >> 4;
    int row0 = (lr)     * BATCH + b;
    int row1 = (lr + 8) * BATCH + b;
    #pragma unroll
    for (int nt = 0; nt < 8; nt++) {
        int d = h * DVh + nt * 8 + 2 * qc;
        store_hl(ohi, olo, (size_t)row0 * EMB + d,
                 oacc[nt][0] * inv0, oacc[nt][1] * inv0);
        store_hl(ohi, olo, (size_t)row1 * EMB + d,
                 oacc[nt][2] * inv1, oacc[nt][3] * inv1);
    }
}

// ---------------- launch ------------------------------------------------------
extern "C" void kernel_launch(void* const* d_in, const int* in_sizes, int n_in,
                              void* d_out, int out_size)
{
    (void)in_sizes; (void)n_in; (void)out_size;
    const float* query = (const float*)d_in[0];
    const float* key_  = (const float*)d_in[1];
    const float* value = (const float*)d_in[2];
    const float* Wq    = (const float*)d_in[3];
    const float* bq    = (const float*)d_in[4];
    const float* Wk    = (const float*)d_in[5];
    const float* bk    = (const float*)d_in[6];
    const float* Wv    = (const float*)d_in[7];
    const float* bv    = (const float*)d_in[8];
    const float* Wo    = (const float*)d_in[9];
    const float* bo    = (const float*)d_in[10];
    float* out = (float*)d_out;

    bf16 *inq_hi,*inq_lo,*ink_hi,*ink_lo,*inv_hi,*inv_lo;
    bf16 *wq_hi,*wq_lo,*wk_hi,*wk_lo,*wv_hi,*wv_lo,*wo_hi,*wo_lo;
    bf16 *q_hi,*q_lo,*k_hi,*k_lo,*v_hi,*v_lo,*at_hi,*at_lo;
    float* corr;
    cudaGetSymbolAddress((void**)&inq_hi, g_inq_hi);
    cudaGetSymbolAddress((void**)&inq_lo, g_inq_lo);
    cudaGetSymbolAddress((void**)&ink_hi, g_ink_hi);
    cudaGetSymbolAddress((void**)&ink_lo, g_ink_lo);
    cudaGetSymbolAddress((void**)&inv_hi, g_inv_hi);
    cudaGetSymbolAddress((void**)&inv_lo, g_inv_lo);
    cudaGetSymbolAddress((void**)&wq_hi, g_wq_hi);
    cudaGetSymbolAddress((void**)&wq_lo, g_wq_lo);
    cudaGetSymbolAddress((void**)&wk_hi, g_wk_hi);
    cudaGetSymbolAddress((void**)&wk_lo, g_wk_lo);
    cudaGetSymbolAddress((void**)&wv_hi, g_wv_hi);
    cudaGetSymbolAddress((void**)&wv_lo, g_wv_lo);
    cudaGetSymbolAddress((void**)&wo_hi, g_wo_hi);
    cudaGetSymbolAddress((void**)&wo_lo, g_wo_lo);
    cudaGetSymbolAddress((void**)&q_hi, g_q_hi);
    cudaGetSymbolAddress((void**)&q_lo, g_q_lo);
    cudaGetSymbolAddress((void**)&k_hi, g_k_hi);
    cudaGetSymbolAddress((void**)&k_lo, g_k_lo);
    cudaGetSymbolAddress((void**)&v_hi, g_v_hi);
    cudaGetSymbolAddress((void**)&v_lo, g_v_lo);
    cudaGetSymbolAddress((void**)&at_hi, g_at_hi);
    cudaGetSymbolAddress((void**)&at_lo, g_at_lo);
    cudaGetSymbolAddress((void**)&corr, g_corr);

    const size_t ATTN_SMEM =
        (size_t)2 * 64 * 136 * sizeof(bf16) + (size_t)2 * 32 * 72 * sizeof(uint32_t);
    cudaFuncSetAttribute(attn_mma, cudaFuncAttributeMaxDynamicSharedMemorySize,
                         (int)ATTN_SMEM);

    build_ws_kernel<<<(NH * L_SEQ + 255) / 256, 256>>>();

    const int NIN = NROWS * EMB;
    cvt_kernel<<<(NIN + 255) / 256, 256>>>(query, inq_hi, inq_lo, NIN);
    cvt_kernel<<<(NIN + 255) / 256, 256>>>(key_,  ink_hi, ink_lo, NIN);
    cvt_kernel<<<(NIN + 255) / 256, 256>>>(value, inv_hi, inv_lo, NIN);
    cvt_kernel<<<(QKD * EMB + 255) / 256, 256>>>(Wq, wq_hi, wq_lo, QKD * EMB);
    cvt_kernel<<<(QKD * EMB + 255) / 256, 256>>>(Wk, wk_hi, wk_lo, QKD * EMB);
    cvt_kernel<<<(EMB * EMB + 255) / 256, 256>>>(Wv, wv_hi, wv_lo, EMB * EMB);
    cvt_kernel<<<(EMB * EMB + 255) / 256, 256>>>(Wo, wo_hi, wo_lo, EMB * EMB);

    float scale = 1.0f / sqrtf((float)QKD);
    mma_gemm<1><<<dim3(QKD / 128, NROWS / 128), 256>>>(
        inq_hi, inq_lo, wq_hi, wq_lo, bq, nullptr, q_hi, q_lo, QKD, EMB, scale);
    mma_gemm<1><<<dim3(QKD / 128, NROWS / 128), 256>>>(
        ink_hi, ink_lo, wk_hi, wk_lo, bk, nullptr, k_hi, k_lo, QKD, EMB, 1.0f);
    mma_gemm<2><<<dim3(EMB / 128, NROWS / 128), 256>>>(
        inv_hi, inv_lo, wv_hi, wv_lo, bv, nullptr, v_hi, v_lo, EMB, EMB, 1.0f);

    corr_kernel<<<dim3(L_SEQ / 128, BATCH * NH), 256>>>(
        q_hi, q_lo, k_hi, k_lo, corr);

    attn_mma<<<dim3(L_SEQ / 64, BATCH * NH), 128, ATTN_SMEM>>>(
        q_hi, q_lo, k_hi, k_lo, v_hi, v_lo, corr, at_hi, at_lo);

    mma_gemm<0><<<dim3(EMB / 128, NROWS / 128), 256>>>(
        at_hi, at_lo, wo_hi, wo_lo, bo, out, nullptr, nullptr, EMB, EMB, 1.0f);
}

// round 8
// speedup vs baseline: 3.4264x; 1.5830x over previous
#include <cuda_runtime.h>
#include <cuda_bf16.h>
#include <stdint.h>
#include <math.h>

#define L_SEQ 2048
#define BATCH 2
#define EMB   1024
#define NH    16
#define DQKh  128
#define QKD   2048
#define DVh   64
#define NROWS 4096

typedef __nv_bfloat16 bf16;

// ---------------- scratch (static device globals; no allocation) -------------
__device__ bf16 g_inq_hi[(size_t)NROWS*EMB];
__device__ bf16 g_inq_lo[(size_t)NROWS*EMB];
__device__ bf16 g_ink_hi[(size_t)NROWS*EMB];
__device__ bf16 g_ink_lo[(size_t)NROWS*EMB];
__device__ bf16 g_inv_hi[(size_t)NROWS*EMB];
__device__ bf16 g_inv_lo[(size_t)NROWS*EMB];
__device__ bf16 g_wq_hi[(size_t)QKD*EMB];
__device__ bf16 g_wq_lo[(size_t)QKD*EMB];
__device__ bf16 g_wk_hi[(size_t)QKD*EMB];
__device__ bf16 g_wk_lo[(size_t)QKD*EMB];
__device__ bf16 g_wv_hi[(size_t)EMB*EMB];
__device__ bf16 g_wv_lo[(size_t)EMB*EMB];
__device__ bf16 g_wo_hi[(size_t)EMB*EMB];
__device__ bf16 g_wo_lo[(size_t)EMB*EMB];
__device__ bf16 g_q_hi[(size_t)BATCH*NH*L_SEQ*DQKh];
__device__ bf16 g_q_lo[(size_t)BATCH*NH*L_SEQ*DQKh];
__device__ bf16 g_k_hi[(size_t)BATCH*NH*L_SEQ*DQKh];   // pre-masked
__device__ bf16 g_k_lo[(size_t)BATCH*NH*L_SEQ*DQKh];   // pre-masked
__device__ bf16 g_v_hi[(size_t)BATCH*NH*L_SEQ*DVh];
__device__ bf16 g_v_lo[(size_t)BATCH*NH*L_SEQ*DVh];
__device__ uint32_t g_vp_hi[(size_t)BATCH*NH*(L_SEQ/2)*DVh]; // paired (s,s+1)
__device__ uint32_t g_vp_lo[(size_t)BATCH*NH*(L_SEQ/2)*DVh];
__device__ float g_kg[(size_t)BATCH*NH*32*DQKh];       // unmasked global k rows
__device__ bf16 g_at_hi[(size_t)NROWS*EMB];
__device__ bf16 g_at_lo[(size_t)NROWS*EMB];
__device__ float g_corr[(size_t)BATCH*NH*L_SEQ*32];
__device__ int   g_ws[NH*L_SEQ];

// ---------------- asm helpers -------------------------------------------------
__device__ __forceinline__ void mma_bf16(float c[4], const uint32_t a[4],
                                         uint32_t b0, uint32_t b1) {
    asm volatile(
        "mma.sync.aligned.m16n8k16.row.col.f32.bf16.bf16.f32 "
        "{%0,%1,%2,%3},{%4,%5,%6,%7},{%8,%9},{%0,%1,%2,%3};"
        : "+f"(c[0]), "+f"(c[1]), "+f"(c[2]), "+f"(c[3])
        : "r"(a[0]), "r"(a[1]), "r"(a[2]), "r"(a[3]), "r"(b0), "r"(b1));
}

#define CP16(dst, src) \
    asm volatile("cp.async.cg.shared.global [%0], [%1], 16;" \
                 :: "r"(dst), "l"(src))
#define CP_COMMIT() asm volatile("cp.async.commit_group;")
#define CP_WAIT1()  asm volatile("cp.async.wait_group 1;")
#define CP_WAIT0()  asm volatile("cp.async.wait_group 0;")

__device__ __forceinline__ uint32_t mpair(uint32_t v, int d, int ws) {
    uint32_t m = 0;
    if ((unsigned)(d - ws) < 32u)     m |= 0x0000FFFFu;
    if ((unsigned)(d + 1 - ws) < 32u) m |= 0xFFFF0000u;
    return v & m;
}

__device__ __forceinline__ void split_pack(float x, float y,
                                           uint32_t& hi, uint32_t& lo) {
    __nv_bfloat16 hx = __float2bfloat16(x), hy = __float2bfloat16(y);
    __nv_bfloat162 ph; ph.x = hx; ph.y = hy;
    hi = *(uint32_t*)&ph;
    __nv_bfloat162 pl;
    pl.x = __float2bfloat16(x - __bfloat162float(hx));
    pl.y = __float2bfloat16(y - __bfloat162float(hy));
    lo = *(uint32_t*)&pl;
}

__device__ __forceinline__ void store_hl(bf16* hip, bf16* lop, size_t idx,
                                         float v0, float v1) {
    __nv_bfloat16 h0 = __float2bfloat16(v0), h1 = __float2bfloat16(v1);
    __nv_bfloat162 hh; hh.x = h0; hh.y = h1;
    *(__nv_bfloat162*)(hip + idx) = hh;
    __nv_bfloat162 ll;
    ll.x = __float2bfloat16(v0 - __bfloat162float(h0));
    ll.y = __float2bfloat16(v1 - __bfloat162float(h1));
    *(__nv_bfloat162*)(lop + idx) = ll;
}

// ---------------- setup kernels ----------------------------------------------
__global__ void build_ws_kernel() {
    int idx = blockIdx.x * blockDim.x + threadIdx.x;
    if (idx >= NH * L_SEQ) return;
    int h = idx / L_SEQ, l = idx % L_SEQ;
    int ws = 0;
    if (h > 0) {
        int rn = 96 / h + 1;
        int i = l / rn, m = l % rn;
        int mm = (i & 1) ? (rn - 1 - m) : m;
        ws = mm * h;
    }
    g_ws[idx] = ws;
}

__global__ void cvt_kernel(const float* __restrict__ src, bf16* __restrict__ hi,
                           bf16* __restrict__ lo, int n) {
    int i = blockIdx.x * blockDim.x + threadIdx.x;
    if (i < n) {
        float x = src[i];
        bf16 h = __float2bfloat16(x);
        hi[i] = h;
        lo[i] = __float2bfloat16(x - __bfloat162float(h));
    }
}

// pack V planes [y][s][d] -> paired u32 [y][s2][d] = (v[2s2][d], v[2s2+1][d])
__global__ void vpack_kernel(const bf16* __restrict__ vhi,
                             const bf16* __restrict__ vlo,
                             uint32_t* __restrict__ phi,
                             uint32_t* __restrict__ plo) {
    int i = blockIdx.x * blockDim.x + threadIdx.x;
    if (i >= BATCH * NH * (L_SEQ / 2) * DVh) return;
    int d = i & 63;
    int s2 = (i >> 6) & (L_SEQ / 2 - 1);
    int y = i >> 16;
    size_t src = ((size_t)y * L_SEQ + 2 * s2) * DVh + d;
    __nv_bfloat162 h2; h2.x = vhi[src]; h2.y = vhi[src + DVh];
    phi[i] = *(uint32_t*)&h2;
    __nv_bfloat162 l2; l2.x = vlo[src]; l2.y = vlo[src + DVh];
    plo[i] = *(uint32_t*)&l2;
}

// ---------------- MMA GEMM v2: 128x128 block, 4 warps 64x64, cp.async x2 -----
// OMODE 0: fp32 out [M,N]
// OMODE 1: relu*scale -> bf16 hi/lo planes [(b h) l d], D=128  (q, unmasked)
// OMODE 2: linear     -> bf16 hi/lo planes [(b h) l d], D=64   (v)
// OMODE 3: relu -> MASKED bf16 planes D=128 (k) + unmasked fp32 g_kg side rows
template <int OMODE>
__global__ void __launch_bounds__(128) mma_gemm(
    const bf16* __restrict__ Ahi, const bf16* __restrict__ Alo,
    const bf16* __restrict__ Whi, const bf16* __restrict__ Wlo,
    const float* __restrict__ bias,
    float* __restrict__ Cf, bf16* __restrict__ Ohi, bf16* __restrict__ Olo,
    float* __restrict__ kg,
    int N, int K, float scale)
{
    extern __shared__ bf16 gsm[];
    int tid = threadIdx.x;
    int wid = tid >> 5, lane = tid & 31;
    int r = lane >> 2, qc = lane & 3;
    int warp_m = (wid >> 1) * 64, warp_n = (wid & 1) * 64;
    int m0 = blockIdx.y * 128, n0 = blockIdx.x * 128;

    const bf16* pAh = Ahi + (size_t)m0 * K;
    const bf16* pAl = Alo + (size_t)m0 * K;
    const bf16* pWh = Whi + (size_t)n0 * K;
    const bf16* pWl = Wlo + (size_t)n0 * K;

    uint32_t sb = (uint32_t)__cvta_generic_to_shared(gsm);

    // stage layout (bf16 elems): Ah[3072] Al[3072] Wh[3072] Wl[3072]; stride 24
    auto load_stage = [&](int kt, uint32_t sbase) {
        #pragma unroll
        for (int i = 0; i < 2; i++) {
            int c = tid + i * 128;
            int row = c >> 1, half = (c & 1) * 8;
            uint32_t dst = sbase + (uint32_t)(row * 24 + half) * 2;
            size_t off = (size_t)row * K + kt + half;
            CP16(dst,         pAh + off);
            CP16(dst +  6144, pAl + off);
            CP16(dst + 12288, pWh + off);
            CP16(dst + 18432, pWl + off);
        }
    };

    load_stage(0, sb);
    CP_COMMIT();

    float acc[4][8][4] = {};
    int T = K >> 4;
    for (int t = 0; t < T; t++) {
        if (t + 1 < T) { load_stage((t + 1) << 4, sb + ((t + 1) & 1) * 24576); CP_COMMIT(); }
        if (t + 1 < T) { CP_WAIT1(); } else { CP_WAIT0(); }
        __syncthreads();

        bf16* sAh = gsm + (t & 1) * 12288;
        bf16* sAl = sAh + 3072;
        bf16* sWh = sAl + 3072;
        bf16* sWl = sWh + 3072;

        uint32_t af[2][4][4];
        #pragma unroll
        for (int mt = 0; mt < 4; mt++) {
            int row = warp_m + mt * 16 + r;
            af[0][mt][0] = *(const uint32_t*)&sAh[row * 24 + 2 * qc];
            af[0][mt][1] = *(const uint32_t*)&sAh[(row + 8) * 24 + 2 * qc];
            af[0][mt][2] = *(const uint32_t*)&sAh[row * 24 + 2 * qc + 8];
            af[0][mt][3] = *(const uint32_t*)&sAh[(row + 8) * 24 + 2 * qc + 8];
            af[1][mt][0] = *(const uint32_t*)&sAl[row * 24 + 2 * qc];
            af[1][mt][1] = *(const uint32_t*)&sAl[(row + 8) * 24 + 2 * qc];
            af[1][mt][2] = *(const uint32_t*)&sAl[row * 24 + 2 * qc + 8];
            af[1][mt][3] = *(const uint32_t*)&sAl[(row + 8) * 24 + 2 * qc + 8];
        }
        #pragma unroll
        for (int nt = 0; nt < 8; nt++) {
            int wrow = warp_n + nt * 8 + r;
            uint32_t bh0 = *(const uint32_t*)&sWh[wrow * 24 + 2 * qc];
            uint32_t bh1 = *(const uint32_t*)&sWh[wrow * 24 + 2 * qc + 8];
            uint32_t bl0 = *(const uint32_t*)&sWl[wrow * 24 + 2 * qc];
            uint32_t bl1 = *(const uint32_t*)&sWl[wrow * 24 + 2 * qc + 8];
            #pragma unroll
            for (int mt = 0; mt < 4; mt++) {
                mma_bf16(acc[mt][nt], af[0][mt], bh0, bh1);
                mma_bf16(acc[mt][nt], af[0][mt], bl0, bl1);
                mma_bf16(acc[mt][nt], af[1][mt], bh0, bh1);
            }
        }
        __syncthreads();
    }

    #pragma unroll
    for (int mt = 0; mt < 4; mt++) {
        #pragma unroll
        for (int nt = 0; nt < 8; nt++) {
            int row0 = m0 + warp_m + mt * 16 + r;
            int row1 = row0 + 8;
            int col  = n0 + warp_n + nt * 8 + 2 * qc;
            float b0f = bias[col], b1f = bias[col + 1];
            float v00 = acc[mt][nt][0] + b0f, v01 = acc[mt][nt][1] + b1f;
            float v10 = acc[mt][nt][2] + b0f, v11 = acc[mt][nt][3] + b1f;
            if (OMODE == 1 || OMODE == 3) {
                v00 = fmaxf(v00, 0.f) * scale; v01 = fmaxf(v01, 0.f) * scale;
                v10 = fmaxf(v10, 0.f) * scale; v11 = fmaxf(v11, 0.f) * scale;
            }
            if (OMODE == 0) {
                *(float2*)(Cf + (size_t)row0 * N + col) = make_float2(v00, v01);
                *(float2*)(Cf + (size_t)row1 * N + col) = make_float2(v10, v11);
            } else if (OMODE == 1) {
                int h = col >> 7, d = col & 127;
                store_hl(Ohi, Olo,
                    ((size_t)((row0 & 1) * NH + h) * L_SEQ + (row0 >> 1)) * DQKh + d,
                    v00, v01);
                store_hl(Ohi, Olo,
                    ((size_t)((row1 & 1) * NH + h) * L_SEQ + (row1 >> 1)) * DQKh + d,
                    v10, v11);
            } else if (OMODE == 2) {
                int h = col >> 6, d = col & 63;
                store_hl(Ohi, Olo,
                    ((size_t)((row0 & 1) * NH + h) * L_SEQ + (row0 >> 1)) * DVh + d,
                    v00, v01);
                store_hl(Ohi, Olo,
                    ((size_t)((row1 & 1) * NH + h) * L_SEQ + (row1 >> 1)) * DVh + d,
                    v10, v11);
            } else { // OMODE 3: masked k + global side rows
                int h = col >> 7, d = col & 127;
                int l0i = row0 >> 1, b0i = row0 & 1;
                int l1i = row1 >> 1, b1i = row1 & 1;
                // side buffer for global rows (unmasked, fp32)
                if (l0i < 16 || l0i >= L_SEQ - 16) {
                    int j = (l0i < 16) ? l0i : (l0i - (L_SEQ - 32));
                    size_t o = ((size_t)(b0i * NH + h) * 32 + j) * DQKh + d;
                    kg[o] = v00; kg[o + 1] = v01;
                }
                if (l1i < 16 || l1i >= L_SEQ - 16) {
                    int j = (l1i < 16) ? l1i : (l1i - (L_SEQ - 32));
                    size_t o = ((size_t)(b1i * NH + h) * 32 + j) * DQKh + d;
                    kg[o] = v10; kg[o + 1] = v11;
                }
                if (h != 0) {
                    int ws0 = g_ws[h * L_SEQ + l0i];
                    int ws1 = g_ws[h * L_SEQ + l1i];
                    if ((unsigned)(d - ws0) >= 32u)     v00 = 0.f;
                    if ((unsigned)(d + 1 - ws0) >= 32u) v01 = 0.f;
                    if ((unsigned)(d - ws1) >= 32u)     v10 = 0.f;
                    if ((unsigned)(d + 1 - ws1) >= 32u) v11 = 0.f;
                }
                store_hl(Ohi, Olo,
                    ((size_t)(b0i * NH + h) * L_SEQ + l0i) * DQKh + d, v00, v01);
                store_hl(Ohi, Olo,
                    ((size_t)(b1i * NH + h) * L_SEQ + l1i) * DQKh + d, v10, v11);
            }
        }
    }
}

// ---------------- global-key correction: corr[y,l,j] = q[l]·kg[j] ------------
__global__ void __launch_bounds__(256) corr_kernel(
    const bf16* __restrict__ qhi, const bf16* __restrict__ qlo,
    const float* __restrict__ kg, float* __restrict__ corr)
{
    __shared__ float sKg[32][128];
    int tid = threadIdx.x;
    int y = blockIdx.y;
    int l0 = blockIdx.x * 128;

    for (int i = tid; i < 32 * 128; i += 256)
        sKg[i >> 7][i & 127] = kg[(size_t)y * 32 * 128 + i];
    __syncthreads();

    int l = l0 + (tid >> 1);
    int jb = (tid & 1) * 16;
    float acc[16] = {};
    size_t qb = ((size_t)y * L_SEQ + l) * DQKh;
    for (int d = 0; d < 128; d += 2) {
        uint32_t ph = *(const uint32_t*)(qhi + qb + d);
        uint32_t pl = *(const uint32_t*)(qlo + qb + d);
        __nv_bfloat162 h2 = *(__nv_bfloat162*)&ph;
        __nv_bfloat162 l2 = *(__nv_bfloat162*)&pl;
        float q0 = __bfloat162float(h2.x) + __bfloat162float(l2.x);
        float q1 = __bfloat162float(h2.y) + __bfloat162float(l2.y);
        #pragma unroll
        for (int j = 0; j < 16; j++)
            acc[j] += q0 * sKg[jb + j][d] + q1 * sKg[jb + j][d + 1];
    }
    float* cp = corr + ((size_t)y * L_SEQ + l) * 32 + jb;
    #pragma unroll
    for (int j = 0; j < 16; j++) cp[j] = acc[j];
}

// ---------------- attention v2: pre-masked K, paired V, cp.async x2 ----------
// grid (L/64, B*NH), 128 threads (4 warps x 16 q-rows). Q frags in registers.
#define AT_KHI 0
#define AT_KLO 17408
#define AT_VHI 34816
#define AT_VLO 44032
#define AT_STAGE 53248

__global__ void __launch_bounds__(128) attn_mma(
    const bf16* __restrict__ qhi, const bf16* __restrict__ qlo,
    const bf16* __restrict__ khi, const bf16* __restrict__ klo,
    const uint32_t* __restrict__ vphi, const uint32_t* __restrict__ vplo,
    const float* __restrict__ corr,
    bf16* __restrict__ ohi, bf16* __restrict__ olo)
{
    extern __shared__ uint8_t sraw[];
    int tid = threadIdx.x;
    int wid = tid >> 5, lane = tid & 31;
    int r = lane >> 2, qc = lane & 3;
    int y = blockIdx.y;
    int h = y & 15;
    int l0 = blockIdx.x * 64;
    int lr = l0 + wid * 16 + r;

    uint32_t sb = (uint32_t)__cvta_generic_to_shared(sraw);

    auto load_stage = [&](int st, uint32_t sbase) {
        int s0 = st * 64;
        size_t kbase = ((size_t)y * L_SEQ + s0) * DQKh;
        #pragma unroll
        for (int i = 0; i < 8; i++) {
            int c = tid + i * 128;
            int row = c >> 4, ch = (c & 15) * 8;
            uint32_t dst = sbase + (uint32_t)(row * 272 + ch * 2);
            CP16(dst + AT_KHI, khi + kbase + row * 128 + ch);
            CP16(dst + AT_KLO, klo + kbase + row * 128 + ch);
        }
        size_t vbase = ((size_t)y * (L_SEQ / 2) + st * 32) * DVh;
        #pragma unroll
        for (int i = 0; i < 4; i++) {
            int c = tid + i * 128;
            int s2 = c >> 4, ch = (c & 15) * 4;
            uint32_t dst = sbase + (uint32_t)(s2 * 288 + ch * 4);
            CP16(dst + AT_VHI, vphi + vbase + s2 * 64 + ch);
            CP16(dst + AT_VLO, vplo + vbase + s2 * 64 + ch);
        }
    };

    // masked Q fragments in registers
    uint32_t qa[8][2][4];
    {
        size_t rb0 = ((size_t)y * L_SEQ + lr) * DQKh;
        size_t rb1 = rb0 + 8 * DQKh;
        int ws0 = (h == 0) ? 0 : g_ws[h * L_SEQ + lr];
        int ws1 = (h == 0) ? 0 : g_ws[h * L_SEQ + lr + 8];
        #pragma unroll
        for (int ks = 0; ks < 8; ks++) {
            int d0 = ks * 16 + 2 * qc;
            int d2 = d0 + 8;
            uint32_t a0 = *(const uint32_t*)(qhi + rb0 + d0);
            uint32_t a1 = *(const uint32_t*)(qhi + rb1 + d0);
            uint32_t a2 = *(const uint32_t*)(qhi + rb0 + d2);
            uint32_t a3 = *(const uint32_t*)(qhi + rb1 + d2);
            uint32_t c0 = *(const uint32_t*)(qlo + rb0 + d0);
            uint32_t c1 = *(const uint32_t*)(qlo + rb1 + d0);
            uint32_t c2 = *(const uint32_t*)(qlo + rb0 + d2);
            uint32_t c3 = *(const uint32_t*)(qlo + rb1 + d2);
            if (h != 0) {
                a0 = mpair(a0, d0, ws0); a1 = mpair(a1, d0, ws1);
                a2 = mpair(a2, d2, ws0); a3 = mpair(a3, d2, ws1);
                c0 = mpair(c0, d0, ws0); c1 = mpair(c1, d0, ws1);
                c2 = mpair(c2, d2, ws0); c3 = mpair(c3, d2, ws1);
            }
            qa[ks][0][0] = a0; qa[ks][0][1] = a1;
            qa[ks][0][2] = a2; qa[ks][0][3] = a3;
            qa[ks][1][0] = c0; qa[ks][1][1] = c1;
            qa[ks][1][2] = c2; qa[ks][1][3] = c3;
        }
    }

    load_stage(0, sb);
    CP_COMMIT();

    float oacc[8][4] = {};
    float den0 = 0.f, den1 = 0.f;

    for (int st = 0; st < 32; st++) {
        if (st + 1 < 32) { load_stage(st + 1, sb + ((st + 1) & 1) * AT_STAGE); CP_COMMIT(); }
        if (st + 1 < 32) { CP_WAIT1(); } else { CP_WAIT0(); }
        __syncthreads();

        uint8_t* stg = sraw + (st & 1) * AT_STAGE;
        bf16* sKhi = (bf16*)(stg + AT_KHI);
        bf16* sKlo = (bf16*)(stg + AT_KLO);
        uint32_t* sVhiP = (uint32_t*)(stg + AT_VHI);
        uint32_t* sVloP = (uint32_t*)(stg + AT_VLO);

        // S = Qmasked @ Kmasked^T (3-term split)
        float sacc[8][4] = {};
        #pragma unroll
        for (int ks = 0; ks < 8; ks++) {
            #pragma unroll
            for (int nt = 0; nt < 8; nt++) {
                int so = (nt * 8 + r) * 136 + ks * 16 + 2 * qc;
                uint32_t bh0 = *(const uint32_t*)&sKhi[so];
                uint32_t bh1 = *(const uint32_t*)&sKhi[so + 8];
                uint32_t bl0 = *(const uint32_t*)&sKlo[so];
                uint32_t bl1 = *(const uint32_t*)&sKlo[so + 8];
                mma_bf16(sacc[nt], qa[ks][0], bh0, bh1);
                mma_bf16(sacc[nt], qa[ks][0], bl0, bl1);
                mma_bf16(sacc[nt], qa[ks][1], bh0, bh1);
            }
        }

        // global-key correction
        if (st == 0) {
            #pragma unroll
            for (int nt = 0; nt < 2; nt++) {
                size_t c0i = ((size_t)y * L_SEQ + lr) * 32 + nt * 8 + 2 * qc;
                size_t c1i = c0i + 8 * 32;
                sacc[nt][0] += corr[c0i]; sacc[nt][1] += corr[c0i + 1];
                sacc[nt][2] += corr[c1i]; sacc[nt][3] += corr[c1i + 1];
            }
        } else if (st == 31) {
            #pragma unroll
            for (int i2 = 0; i2 < 2; i2++) {
                int nt = 6 + i2;
                size_t c0i = ((size_t)y * L_SEQ + lr) * 32 + 16 + i2 * 8 + 2 * qc;
                size_t c1i = c0i + 8 * 32;
                sacc[nt][0] += corr[c0i]; sacc[nt][1] += corr[c0i + 1];
                sacc[nt][2] += corr[c1i]; sacc[nt][3] += corr[c1i + 1];
            }
        }

        // denominator partials
        #pragma unroll
        for (int nt = 0; nt < 8; nt++) {
            den0 += sacc[nt][0] + sacc[nt][1];
            den1 += sacc[nt][2] + sacc[nt][3];
        }

        // O += S @ V (S frags re-split to bf16 as A fragments)
        #pragma unroll
        for (int kk = 0; kk < 4; kk++) {
            uint32_t ahi[4], alo[4];
            split_pack(sacc[2 * kk][0],     sacc[2 * kk][1],     ahi[0], alo[0]);
            split_pack(sacc[2 * kk][2],     sacc[2 * kk][3],     ahi[1], alo[1]);
            split_pack(sacc[2 * kk + 1][0], sacc[2 * kk + 1][1], ahi[2], alo[2]);
            split_pack(sacc[2 * kk + 1][2], sacc[2 * kk + 1][3], ahi[3], alo[3]);
            #pragma unroll
            for (int nt = 0; nt < 8; nt++) {
                int vo = (kk * 8 + qc) * 72 + nt * 8 + r;
                uint32_t bh0 = sVhiP[vo], bh1 = sVhiP[vo + 4 * 72];
                uint32_t bl0 = sVloP[vo], bl1 = sVloP[vo + 4 * 72];
                mma_bf16(oacc[nt], ahi, bh0, bh1);
                mma_bf16(oacc[nt], ahi, bl0, bl1);
                mma_bf16(oacc[nt], alo, bh0, bh1);
            }
        }
        __syncthreads();
    }

    den0 += __shfl_xor_sync(0xffffffffu, den0, 1);
    den0 += __shfl_xor_sync(0xffffffffu, den0, 2);
    den1 += __shfl_xor_sync(0xffffffffu, den1, 1);
    den1 += __shfl_xor_sync(0xffffffffu, den1, 2);
    float inv0 = 1.0f / fmaxf(den0, 1e-12f);
    float inv1 = 1.0f / fmaxf(den1, 1e-12f);

    int b = y >> 4;
    int row0 = (lr)     * BATCH + b;
    int row1 = (lr + 8) * BATCH + b;
    #pragma unroll
    for (int nt = 0; nt < 8; nt++) {
        int d = h * DVh + nt * 8 + 2 * qc;
        store_hl(ohi, olo, (size_t)row0 * EMB + d,
                 oacc[nt][0] * inv0, oacc[nt][1] * inv0);
        store_hl(ohi, olo, (size_t)row1 * EMB + d,
                 oacc[nt][2] * inv1, oacc[nt][3] * inv1);
    }
}

// ---------------- launch ------------------------------------------------------
extern "C" void kernel_launch(void* const* d_in, const int* in_sizes, int n_in,
                              void* d_out, int out_size)
{
    (void)in_sizes; (void)n_in; (void)out_size;
    const float* query = (const float*)d_in[0];
    const float* key_  = (const float*)d_in[1];
    const float* value = (const float*)d_in[2];
    const float* Wq    = (const float*)d_in[3];
    const float* bq    = (const float*)d_in[4];
    const float* Wk    = (const float*)d_in[5];
    const float* bk    = (const float*)d_in[6];
    const float* Wv    = (const float*)d_in[7];
    const float* bv    = (const float*)d_in[8];
    const float* Wo    = (const float*)d_in[9];
    const float* bo    = (const float*)d_in[10];
    float* out = (float*)d_out;

    bf16 *inq_hi,*inq_lo,*ink_hi,*ink_lo,*inv_hi,*inv_lo;
    bf16 *wq_hi,*wq_lo,*wk_hi,*wk_lo,*wv_hi,*wv_lo,*wo_hi,*wo_lo;
    bf16 *q_hi,*q_lo,*k_hi,*k_lo,*v_hi,*v_lo,*at_hi,*at_lo;
    uint32_t *vp_hi,*vp_lo;
    float *corr,*kg;
    cudaGetSymbolAddress((void**)&inq_hi, g_inq_hi);
    cudaGetSymbolAddress((void**)&inq_lo, g_inq_lo);
    cudaGetSymbolAddress((void**)&ink_hi, g_ink_hi);
    cudaGetSymbolAddress((void**)&ink_lo, g_ink_lo);
    cudaGetSymbolAddress((void**)&inv_hi, g_inv_hi);
    cudaGetSymbolAddress((void**)&inv_lo, g_inv_lo);
    cudaGetSymbolAddress((void**)&wq_hi, g_wq_hi);
    cudaGetSymbolAddress((void**)&wq_lo, g_wq_lo);
    cudaGetSymbolAddress((void**)&wk_hi, g_wk_hi);
    cudaGetSymbolAddress((void**)&wk_lo, g_wk_lo);
    cudaGetSymbolAddress((void**)&wv_hi, g_wv_hi);
    cudaGetSymbolAddress((void**)&wv_lo, g_wv_lo);
    cudaGetSymbolAddress((void**)&wo_hi, g_wo_hi);
    cudaGetSymbolAddress((void**)&wo_lo, g_wo_lo);
    cudaGetSymbolAddress((void**)&q_hi, g_q_hi);
    cudaGetSymbolAddress((void**)&q_lo, g_q_lo);
    cudaGetSymbolAddress((void**)&k_hi, g_k_hi);
    cudaGetSymbolAddress((void**)&k_lo, g_k_lo);
    cudaGetSymbolAddress((void**)&v_hi, g_v_hi);
    cudaGetSymbolAddress((void**)&v_lo, g_v_lo);
    cudaGetSymbolAddress((void**)&vp_hi, g_vp_hi);
    cudaGetSymbolAddress((void**)&vp_lo, g_vp_lo);
    cudaGetSymbolAddress((void**)&at_hi, g_at_hi);
    cudaGetSymbolAddress((void**)&at_lo, g_at_lo);
    cudaGetSymbolAddress((void**)&corr, g_corr);
    cudaGetSymbolAddress((void**)&kg, g_kg);

    const int GEMM_SMEM = 49152;
    cudaFuncSetAttribute(mma_gemm<0>, cudaFuncAttributeMaxDynamicSharedMemorySize, GEMM_SMEM);
    cudaFuncSetAttribute(mma_gemm<1>, cudaFuncAttributeMaxDynamicSharedMemorySize, GEMM_SMEM);
    cudaFuncSetAttribute(mma_gemm<2>, cudaFuncAttributeMaxDynamicSharedMemorySize, GEMM_SMEM);
    cudaFuncSetAttribute(mma_gemm<3>, cudaFuncAttributeMaxDynamicSharedMemorySize, GEMM_SMEM);
    const int ATTN_SMEM = 2 * AT_STAGE;
    cudaFuncSetAttribute(attn_mma, cudaFuncAttributeMaxDynamicSharedMemorySize, ATTN_SMEM);

    build_ws_kernel<<<(NH * L_SEQ + 255) / 256, 256>>>();

    const int NIN = NROWS * EMB;
    cvt_kernel<<<(NIN + 255) / 256, 256>>>(query, inq_hi, inq_lo, NIN);
    cvt_kernel<<<(NIN + 255) / 256, 256>>>(key_,  ink_hi, ink_lo, NIN);
    cvt_kernel<<<(NIN + 255) / 256, 256>>>(value, inv_hi, inv_lo, NIN);
    cvt_kernel<<<(QKD * EMB + 255) / 256, 256>>>(Wq, wq_hi, wq_lo, QKD * EMB);
    cvt_kernel<<<(QKD * EMB + 255) / 256, 256>>>(Wk, wk_hi, wk_lo, QKD * EMB);
    cvt_kernel<<<(EMB * EMB + 255) / 256, 256>>>(Wv, wv_hi, wv_lo, EMB * EMB);
    cvt_kernel<<<(EMB * EMB + 255) / 256, 256>>>(Wo, wo_hi, wo_lo, EMB * EMB);

    float scale = 1.0f / sqrtf((float)QKD);
    // q (unmasked planes)
    mma_gemm<1><<<dim3(QKD / 128, NROWS / 128), 128, GEMM_SMEM>>>(
        inq_hi, inq_lo, wq_hi, wq_lo, bq, nullptr, q_hi, q_lo, nullptr,
        QKD, EMB, scale);
    // k (masked planes + kg side buffer)
    mma_gemm<3><<<dim3(QKD / 128, NROWS / 128), 128, GEMM_SMEM>>>(
        ink_hi, ink_lo, wk_hi, wk_lo, bk, nullptr, k_hi, k_lo, kg,
        QKD, EMB, 1.0f);
    // v
    mma_gemm<2><<<dim3(EMB / 128, NROWS / 128), 128, GEMM_SMEM>>>(
        inv_hi, inv_lo, wv_hi, wv_lo, bv, nullptr, v_hi, v_lo, nullptr,
        EMB, EMB, 1.0f);

    // pack V into paired layout
    const int NVP = BATCH * NH * (L_SEQ / 2) * DVh;
    vpack_kernel<<<(NVP + 255) / 256, 256>>>(v_hi, v_lo, vp_hi, vp_lo);

    corr_kernel<<<dim3(L_SEQ / 128, BATCH * NH), 256>>>(q_hi, q_lo, kg, corr);

    attn_mma<<<dim3(L_SEQ / 64, BATCH * NH), 128, ATTN_SMEM>>>(
        q_hi, q_lo, k_hi, k_lo, vp_hi, vp_lo, corr, at_hi, at_lo);

    // out = attn @ Wo^T + bo
    mma_gemm<0><<<dim3(EMB / 128, NROWS / 128), 128, GEMM_SMEM>>>(
        at_hi, at_lo, wo_hi, wo_lo, bo, out, nullptr, nullptr, nullptr,
        EMB, EMB, 1.0f);
}